// round 14
// baseline (speedup 1.0000x reference)
#include <cuda_runtime.h>
#include <cuda_bf16.h>
#include <math.h>
#include <stdint.h>

#define NN 8192
#define FF 256
#define NE 262144
#define ADJW (NN * (NN / 32))   // 2,097,152 words = 8 MB bitmap

// ---------------- scratch (device globals; no allocation allowed) ----------------
__device__ __align__(256) float    g_meansum[FF];
__device__ __align__(256) float    g_mcor[FF];
__device__ __align__(256) float    g_cov[FF * FF];       // covraw = zh^T zh
__device__ __align__(256) float    g_cor[FF * FF];
__device__ __align__(256) __nv_bfloat16 g_corh[FF * FF];
__device__ __align__(256) float    g_w[NN];
__device__ __align__(256) float    g_z2[NN * FF];        // 8 MB fp32
__device__ __align__(256) __nv_bfloat16 g_zh[NN * FF];   // 4 MB bf16 of z
__device__ __align__(256) signed char g_z2b[NN * FF];    // 2 MB int8 of z2
__device__ __align__(256) float    g_rs[NN];             // per-row quant scale
__device__ __align__(256) float    g_invn[NN];
__device__ __align__(256) unsigned g_adj[ADJW];          // 8 MB adjacency bitmap
__device__ __align__(256) float    g_scores[NN];
__device__ __align__(256) float    g_deg[NN];
__device__ double g_penalty;
__device__ int    g_is64;

__device__ __forceinline__ int load_idx(const void* p, int k, int is64) {
    return is64 ? (int)((const long long*)p)[k] : ((const int*)p)[k];
}

// ---------------- zero scratch + index dtype detection ----------------
__global__ void k_zero(const unsigned* __restrict__ e) {
    int idx = blockIdx.x * blockDim.x + threadIdx.x;
    int stride = gridDim.x * blockDim.x;
    for (int i = idx; i < ADJW; i += stride) g_adj[i] = 0u;
    for (int i = idx; i < FF * FF; i += stride) g_cov[i] = 0.0f;
    for (int i = idx; i < NN; i += stride) { g_scores[i] = 0.0f; g_deg[i] = 0.0f; }
    for (int i = idx; i < FF; i += stride) g_meansum[i] = 0.0f;
    if (idx == 0) g_penalty = 0.0;
    if (blockIdx.x == 0) {
        unsigned acc = 0;
        for (int i = threadIdx.x; i < 2048; i += 256) acc |= e[2 * i + 1];
        int any = __syncthreads_or((int)(acc != 0));
        if (threadIdx.x == 0) g_is64 = any ? 0 : 1;
    }
}

// ---------------- fused: column sums + z -> bf16 ----------------
__global__ void k_meanzh(const float* __restrict__ z) {
    int f = threadIdx.x;
    int r0 = blockIdx.x * 64;
    float s = 0.0f;
    #pragma unroll 8
    for (int r = 0; r < 64; ++r) {
        float v = z[(r0 + r) * FF + f];
        s += v;
        g_zh[(r0 + r) * FF + f] = __float2bfloat16(v);
    }
    atomicAdd(&g_meansum[f], s);
}

// ---------------- per-node weight ----------------
__global__ void k_w(const void* __restrict__ k2u, const void* __restrict__ u2k) {
    int n = blockIdx.x * blockDim.x + threadIdx.x;
    int is64 = g_is64;
    if (n < NN) {
        float a = powf(0.9f, (float)load_idx(k2u, n, is64));
        float b = powf(0.9f, (float)load_idx(u2k, n, is64));
        g_w[n] = a + 1.0f - b;
    }
}

// ---------------- adjacency bitmap + degree ----------------
__global__ void k_adj(const void* __restrict__ ei) {
    int e = blockIdx.x * blockDim.x + threadIdx.x;
    int is64 = g_is64;
    if (e < NE) {
        int i = load_idx(ei, e, is64);
        int j = load_idx(ei, NE + e, is64);
        unsigned b1 = (unsigned)i * NN + (unsigned)j;
        atomicOr(&g_adj[b1 >> 5], 1u << (b1 & 31));
        unsigned b2 = (unsigned)j * NN + (unsigned)i;
        atomicOr(&g_adj[b2 >> 5], 1u << (b2 & 31));
        atomicAdd(&g_deg[i], 1.0f);
    }
}

// ---------------- MMA helpers ----------------
__device__ __forceinline__ void ldsm_x4(unsigned addr, unsigned& r0, unsigned& r1,
                                        unsigned& r2, unsigned& r3) {
    asm volatile("ldmatrix.sync.aligned.m8n8.x4.shared.b16 {%0,%1,%2,%3}, [%4];"
                 : "=r"(r0), "=r"(r1), "=r"(r2), "=r"(r3) : "r"(addr));
}

__device__ __forceinline__ void ldsm_x4t(unsigned addr, unsigned& r0, unsigned& r1,
                                         unsigned& r2, unsigned& r3) {
    asm volatile("ldmatrix.sync.aligned.m8n8.x4.trans.shared.b16 {%0,%1,%2,%3}, [%4];"
                 : "=r"(r0), "=r"(r1), "=r"(r2), "=r"(r3) : "r"(addr));
}

__device__ __forceinline__ void mma16816(float* d, const unsigned* a, const unsigned* b) {
    asm volatile(
        "mma.sync.aligned.m16n8k16.row.col.f32.bf16.bf16.f32 "
        "{%0,%1,%2,%3}, {%4,%5,%6,%7}, {%8,%9}, {%0,%1,%2,%3};"
        : "+f"(d[0]), "+f"(d[1]), "+f"(d[2]), "+f"(d[3])
        : "r"(a[0]), "r"(a[1]), "r"(a[2]), "r"(a[3]), "r"(b[0]), "r"(b[1]));
}

__device__ __forceinline__ void mma16832i(int* d, const unsigned* a, const unsigned* b) {
    asm volatile(
        "mma.sync.aligned.m16n8k32.row.col.s32.s8.s8.s32 "
        "{%0,%1,%2,%3}, {%4,%5,%6,%7}, {%8,%9}, {%0,%1,%2,%3};"
        : "+r"(d[0]), "+r"(d[1]), "+r"(d[2]), "+r"(d[3])
        : "r"(a[0]), "r"(a[1]), "r"(a[2]), "r"(a[3]), "r"(b[0]), "r"(b[1]));
}

__device__ __forceinline__ void cp16(unsigned saddr, const void* gaddr) {
    asm volatile("cp.async.cg.shared.global [%0], [%1], 16;"
                 :: "r"(saddr), "l"(gaddr) : "memory");
}

// ---------------- covraw = zh^T @ zh via HMMA (trans loads), upper tile pairs ----------------
__global__ void __launch_bounds__(256, 2) k_covm() {
    if (blockIdx.x > blockIdx.y) return;
    extern __shared__ char dsm[];
    int i0 = blockIdx.x * 128, j0 = blockIdx.y * 128;
    int r0 = blockIdx.z * 256;
    int tid = threadIdx.x;
    int lane = tid & 31;
    int warp = tid >> 5;
    int wm = warp & 3;
    int wn = warp >> 2;
    unsigned sbase = (unsigned)__cvta_generic_to_shared(dsm);
    unsigned aBase = sbase;
    unsigned bBase = sbase + 32768;
    float acc[2][8][4] = {};

    for (int cc = 0; cc < 2; ++cc) {
        int rr = r0 + cc * 128;
        __syncthreads();
        #pragma unroll
        for (int it = 0; it < 8; ++it) {
            int lin = tid + it * 256;
            int r = lin >> 4, c = lin & 15;
            unsigned soff = (unsigned)(r * 256 + ((c ^ (r & 7)) << 4));
            uint4 va = *((const uint4*)(g_zh + (rr + r) * FF + i0) + c);
            uint4 vb = *((const uint4*)(g_zh + (rr + r) * FF + j0) + c);
            *(uint4*)(dsm + soff) = va;
            *(uint4*)(dsm + 32768 + soff) = vb;
        }
        __syncthreads();
        #pragma unroll
        for (int ks = 0; ks < 8; ++ks) {
            int k0 = ks * 16;
            unsigned a[2][4];
            #pragma unroll
            for (int am = 0; am < 2; ++am) {
                int m0 = wm * 32 + am * 16;
                int rA = k0 + ((lane >> 4) & 1) * 8 + (lane & 7);
                int cA = (m0 >> 3) + ((lane >> 3) & 1);
                unsigned addr = aBase + rA * 256 + ((cA ^ (rA & 7)) << 4);
                ldsm_x4t(addr, a[am][0], a[am][1], a[am][2], a[am][3]);
            }
            unsigned b[8][2];
            #pragma unroll
            for (int bn = 0; bn < 4; ++bn) {
                int n0 = wn * 64 + bn * 16;
                int rB = k0 + ((lane >> 3) & 1) * 8 + (lane & 7);
                int cB = (n0 >> 3) + ((lane >> 4) & 1);
                unsigned addr = bBase + rB * 256 + ((cB ^ (rB & 7)) << 4);
                ldsm_x4t(addr, b[2 * bn][0], b[2 * bn][1], b[2 * bn + 1][0], b[2 * bn + 1][1]);
            }
            #pragma unroll
            for (int am = 0; am < 2; ++am)
                #pragma unroll
                for (int nb = 0; nb < 8; ++nb)
                    mma16816(acc[am][nb], a[am], b[nb]);
        }
    }

    #pragma unroll
    for (int am = 0; am < 2; ++am) {
        #pragma unroll
        for (int nb = 0; nb < 8; ++nb) {
            #pragma unroll
            for (int e = 0; e < 4; ++e) {
                int rl = wm * 32 + am * 16 + (lane >> 2) + ((e >> 1) << 3);
                int cl = wn * 64 + nb * 8 + ((lane & 3) << 1) + (e & 1);
                atomicAdd(&g_cov[(i0 + rl) * FF + (j0 + cl)], acc[am][nb][e]);
            }
        }
    }
}

// ---------------- cor: mean-correct covraw, normalize, clamp ----------------
__global__ void k_cor() {
    int idx = blockIdx.x * blockDim.x + threadIdx.x;
    int i = idx >> 8, j = idx & 255;
    int a = min(i, j), b = max(i, j);
    const float inv = 1.0f / (float)NN;
    float mi = g_meansum[i] * inv, mj = g_meansum[j] * inv;
    float di = g_cov[i * FF + i] - (float)NN * mi * mi;
    float dj = g_cov[j * FF + j] - (float)NN * mj * mj;
    float num = g_cov[a * FF + b] - (float)NN * mi * mj;
    float v = num / sqrtf(di * dj);
    if (v != v) v = 0.0f;
    v = fminf(1.0f, fmaxf(-1.0f, v));
    if (i == j) v = 0.0f;
    g_cor[idx] = v;
    g_corh[idx] = __float2bfloat16(v);
}

// ---------------- mcor[c] = sum_k mean[k] * cor[k,c]  (warp per column) ----------------
__global__ void k_mcor() {
    int warp = threadIdx.x >> 5;
    int lane = threadIdx.x & 31;
    int c = blockIdx.x * 8 + warp;
    const float inv = 1.0f / (float)NN;
    float s = 0.0f;
    #pragma unroll
    for (int k = lane; k < FF; k += 32) s += g_meansum[k] * inv * g_cor[k * FF + c];
    #pragma unroll
    for (int o = 16; o; o >>= 1) s += __shfl_down_sync(0xffffffffu, s, o);
    if (lane == 0) g_mcor[c] = s;
}

// ---------------- z2 = z + 0.01*w*(zh@corh - mcor) : HMMA + cp.async ----------------
__global__ void __launch_bounds__(256, 2) k_z2m(const float* __restrict__ z) {
    extern __shared__ char dsm[];
    int r0 = blockIdx.x * 128, c0 = blockIdx.y * 128;
    int tid = threadIdx.x;
    int lane = tid & 31;
    int warp = tid >> 5;
    int wm = warp & 3;
    int wn = warp >> 2;
    unsigned sbase = (unsigned)__cvta_generic_to_shared(dsm);

    auto load_slab = [&](int s, int bsel) {
        unsigned aB = sbase + bsel * 16384;
        unsigned bB = sbase + 32768 + bsel * 16384;
        #pragma unroll
        for (int it = 0; it < 4; ++it) {
            int lin = tid + it * 256;
            int r = lin >> 3, c = lin & 7;
            unsigned soff = (unsigned)(r * 128 + ((c ^ (r & 7)) << 4));
            cp16(aB + soff, g_zh + (r0 + r) * FF + s * 64 + c * 8);
            cp16(bB + soff, g_corh + (c0 + r) * FF + s * 64 + c * 8);
        }
        asm volatile("cp.async.commit_group;" ::: "memory");
    };

    float acc[2][8][4] = {};
    load_slab(0, 0);
    #pragma unroll
    for (int s = 0; s < 4; ++s) {
        if (s < 3) {
            load_slab(s + 1, (s + 1) & 1);
            asm volatile("cp.async.wait_group 1;" ::: "memory");
        } else {
            asm volatile("cp.async.wait_group 0;" ::: "memory");
        }
        __syncthreads();
        unsigned aBase = sbase + (s & 1) * 16384;
        unsigned bBase = sbase + 32768 + (s & 1) * 16384;
        #pragma unroll
        for (int ks = 0; ks < 4; ++ks) {
            unsigned a[2][4];
            #pragma unroll
            for (int am = 0; am < 2; ++am) {
                int ra = wm * 32 + am * 16 + (lane & 15);
                int ca = 2 * ks + (lane >> 4);
                unsigned addr = aBase + ra * 128 + ((ca ^ (ra & 7)) << 4);
                ldsm_x4(addr, a[am][0], a[am][1], a[am][2], a[am][3]);
            }
            unsigned b[8][2];
            #pragma unroll
            for (int bn = 0; bn < 4; ++bn) {
                int rb = wn * 64 + bn * 16 + (lane & 7) + ((lane >> 4) << 3);
                int cb = 2 * ks + ((lane >> 3) & 1);
                unsigned addr = bBase + rb * 128 + ((cb ^ (rb & 7)) << 4);
                ldsm_x4(addr, b[2 * bn][0], b[2 * bn][1], b[2 * bn + 1][0], b[2 * bn + 1][1]);
            }
            #pragma unroll
            for (int am = 0; am < 2; ++am)
                #pragma unroll
                for (int nb = 0; nb < 8; ++nb)
                    mma16816(acc[am][nb], a[am], b[nb]);
        }
        __syncthreads();
    }

    #pragma unroll
    for (int am = 0; am < 2; ++am) {
        #pragma unroll
        for (int nb = 0; nb < 8; ++nb) {
            #pragma unroll
            for (int e = 0; e < 4; ++e) {
                int rl = wm * 32 + am * 16 + (lane >> 2) + ((e >> 1) << 3);
                int cl = wn * 64 + nb * 8 + ((lane & 3) << 1) + (e & 1);
                int r = r0 + rl, c = c0 + cl;
                g_z2[r * FF + c] = z[r * FF + c]
                                 + 0.01f * g_w[r] * (acc[am][nb][e] - g_mcor[c]);
            }
        }
    }
}

// ---------------- row norms + diag penalty + int8 quantize ----------------
__global__ void k_norm() {
    int gw = (blockIdx.x * blockDim.x + threadIdx.x) >> 5;
    int lane = threadIdx.x & 31;
    if (gw >= NN) return;
    const float4* p = (const float4*)(g_z2 + gw * FF);
    float4 a = p[lane * 2], b = p[lane * 2 + 1];
    float v[8] = {a.x, a.y, a.z, a.w, b.x, b.y, b.z, b.w};

    float mx = 0.0f, s = 0.0f;
    #pragma unroll
    for (int q = 0; q < 8; ++q) { mx = fmaxf(mx, fabsf(v[q])); s += v[q] * v[q]; }
    #pragma unroll
    for (int o = 16; o; o >>= 1) {
        mx = fmaxf(mx, __shfl_xor_sync(0xffffffffu, mx, o));
        s += __shfl_xor_sync(0xffffffffu, s, o);
    }
    float scale = fmaxf(mx, 1e-20f) * (1.0f / 127.0f);
    float qinv = 127.0f / fmaxf(mx, 1e-20f);
    unsigned w0 = 0, w1 = 0;
    #pragma unroll
    for (int q = 0; q < 4; ++q) {
        int t = __float2int_rn(v[q] * qinv);
        t = max(-127, min(127, t));
        w0 |= ((unsigned)t & 0xffu) << (q * 8);
    }
    #pragma unroll
    for (int q = 0; q < 4; ++q) {
        int t = __float2int_rn(v[4 + q] * qinv);
        t = max(-127, min(127, t));
        w1 |= ((unsigned)t & 0xffu) << (q * 8);
    }
    *((uint2*)(g_z2b + gw * FF) + lane) = make_uint2(w0, w1);

    if (lane == 0) {
        g_rs[gw] = scale;
        g_invn[gw] = 1.0f / fmaxf(sqrtf(s), 1e-8f);
        unsigned bi = (unsigned)gw * NN + (unsigned)gw;
        unsigned bit = (g_adj[bi >> 5] >> (bi & 31)) & 1u;
        if (s > 0.8f && !bit) atomicAdd(&g_penalty, (double)s);
    }
}

// ---------------- per-edge cosine similarity (int8 dp4a) ----------------
__global__ void k_edge(const void* __restrict__ ei) {
    int gw = (blockIdx.x * blockDim.x + threadIdx.x) >> 5;
    int lane = threadIdx.x & 31;
    if (gw >= NE) return;
    int is64 = g_is64;
    int i = load_idx(ei, gw, is64);
    int j = load_idx(ei, NE + gw, is64);
    uint2 ua = *((const uint2*)(g_z2b + i * FF) + lane);
    uint2 ub = *((const uint2*)(g_z2b + j * FF) + lane);
    int d = 0;
    d = __dp4a((int)ua.x, (int)ub.x, d);
    d = __dp4a((int)ua.y, (int)ub.y, d);
    #pragma unroll
    for (int o = 16; o; o >>= 1) d += __shfl_down_sync(0xffffffffu, d, o);
    if (lane == 0)
        atomicAdd(&g_scores[i], (float)d * g_rs[i] * g_rs[j] * g_invn[i] * g_invn[j]);
}

// ---------------- masked similarity GEMM (int8 IMMA + cp.async double buffer) ----------------
__device__ __forceinline__ int cumt(int br) { return br * 64 - (br * (br - 1)) / 2; }

// smem 64KB: A slabs 0/16384, B slabs 32768/49152; slab = 128 rows x 128 int8 (2 slabs = K256)
__global__ void __launch_bounds__(256, 2) k_sim() {
    extern __shared__ char dsm[];
    __shared__ unsigned sAdj[512];
    __shared__ float sRed[256];
    __shared__ float sRsA[128], sRsB[128];

    int t = blockIdx.x;
    int br = (int)(64.5f - sqrtf(64.5f * 64.5f - 2.0f * (float)t));
    if (br < 0) br = 0; if (br > 63) br = 63;
    while (br < 63 && cumt(br + 1) <= t) br++;
    while (br > 0 && cumt(br) > t) br--;
    int bc = br + (t - cumt(br));
    int r0 = br * 128, c0 = bc * 128;

    int tid = threadIdx.x;
    int lane = tid & 31;
    int warp = tid >> 5;
    int wm = warp & 3;
    int wn = warp >> 2;

    for (int s2 = tid; s2 < 512; s2 += 256)
        sAdj[s2] = g_adj[(r0 + (s2 >> 2)) * (NN / 32) + (c0 >> 5) + (s2 & 3)];
    if (tid < 128) { sRsA[tid] = g_rs[r0 + tid]; sRsB[tid] = g_rs[c0 + tid]; }

    unsigned sbase = (unsigned)__cvta_generic_to_shared(dsm);

    auto load_slab = [&](int s, int bsel) {
        unsigned aB = sbase + bsel * 16384;
        unsigned bB = sbase + 32768 + bsel * 16384;
        #pragma unroll
        for (int it = 0; it < 4; ++it) {
            int lin = tid + it * 256;          // 0..1023
            int r = lin >> 3, c = lin & 7;     // row, 16B chunk
            unsigned soff = (unsigned)(r * 128 + ((c ^ (r & 7)) << 4));
            cp16(aB + soff, g_z2b + (r0 + r) * FF + s * 128 + c * 16);
            cp16(bB + soff, g_z2b + (c0 + r) * FF + s * 128 + c * 16);
        }
        asm volatile("cp.async.commit_group;" ::: "memory");
    };

    int acc[2][8][4] = {};
    load_slab(0, 0);
    #pragma unroll
    for (int s = 0; s < 2; ++s) {
        if (s < 1) {
            load_slab(1, 1);
            asm volatile("cp.async.wait_group 1;" ::: "memory");
        } else {
            asm volatile("cp.async.wait_group 0;" ::: "memory");
        }
        __syncthreads();
        unsigned aBase = sbase + s * 16384;
        unsigned bBase = sbase + 32768 + s * 16384;
        #pragma unroll
        for (int ks = 0; ks < 4; ++ks) {       // k32 int8 = 2x16B chunks per step
            unsigned a[2][4];
            #pragma unroll
            for (int am = 0; am < 2; ++am) {
                int ra = wm * 32 + am * 16 + (lane & 15);
                int ca = 2 * ks + (lane >> 4);
                unsigned addr = aBase + ra * 128 + ((ca ^ (ra & 7)) << 4);
                ldsm_x4(addr, a[am][0], a[am][1], a[am][2], a[am][3]);
            }
            unsigned b[8][2];
            #pragma unroll
            for (int bn = 0; bn < 4; ++bn) {
                int rb = wn * 64 + bn * 16 + (lane & 7) + ((lane >> 4) << 3);
                int cb = 2 * ks + ((lane >> 3) & 1);
                unsigned addr = bBase + rb * 128 + ((cb ^ (rb & 7)) << 4);
                ldsm_x4(addr, b[2 * bn][0], b[2 * bn][1], b[2 * bn + 1][0], b[2 * bn + 1][1]);
            }
            #pragma unroll
            for (int am = 0; am < 2; ++am)
                #pragma unroll
                for (int nb = 0; nb < 8; ++nb)
                    mma16832i(acc[am][nb], a[am], b[nb]);
        }
        __syncthreads();
    }

    bool diagBlk = (br == bc);
    float lsum = 0.0f;
    #pragma unroll
    for (int am = 0; am < 2; ++am) {
        #pragma unroll
        for (int nb = 0; nb < 8; ++nb) {
            #pragma unroll
            for (int e = 0; e < 4; ++e) {
                int rl = wm * 32 + am * 16 + (lane >> 2) + ((e >> 1) << 3);
                int cl = wn * 64 + nb * 8 + ((lane & 3) << 1) + (e & 1);
                float val = (float)acc[am][nb][e] * sRsA[rl] * sRsB[cl];
                unsigned bit = (sAdj[rl * 4 + (cl >> 5)] >> (cl & 31)) & 1u;
                if (val > 0.8f && !bit && (!diagBlk || cl > rl)) lsum += val;
            }
        }
    }
    sRed[tid] = lsum;
    __syncthreads();
    for (int o = 128; o; o >>= 1) {
        if (tid < o) sRed[tid] += sRed[tid + o];
        __syncthreads();
    }
    if (tid == 0) atomicAdd(&g_penalty, 2.0 * (double)sRed[0]);
}

// ---------------- final scalar ----------------
__global__ void k_final(float* __restrict__ out) {
    __shared__ double sred[256];
    int tid = threadIdx.x;
    double s = 0.0;
    for (int n = tid; n < NN; n += 256) {
        float d = g_deg[n];
        if (d == 0.0f) d = 1.0f;
        s += (double)(g_scores[n] / d);
    }
    sred[tid] = s;
    __syncthreads();
    for (int o = 128; o; o >>= 1) {
        if (tid < o) sred[tid] += sred[tid + o];
        __syncthreads();
    }
    if (tid == 0) {
        double hom = -sred[0] / (double)NN;
        double pen = g_penalty / ((double)NN * (double)NN);
        out[0] = (float)(hom + pen);
    }
}

// ---------------- launch ----------------
extern "C" void kernel_launch(void* const* d_in, const int* in_sizes, int n_in,
                              void* d_out, int out_size) {
    const float* z   = (const float*)d_in[0];
    const void* ei   = d_in[2];
    const void* k2u  = d_in[3];
    const void* u2k  = d_in[4];
    float* out = (float*)d_out;

    cudaFuncSetAttribute(k_sim, cudaFuncAttributeMaxDynamicSharedMemorySize, 65536);
    cudaFuncSetAttribute(k_z2m, cudaFuncAttributeMaxDynamicSharedMemorySize, 65536);
    cudaFuncSetAttribute(k_covm, cudaFuncAttributeMaxDynamicSharedMemorySize, 65536);

    k_zero<<<2048, 256>>>((const unsigned*)ei);
    k_meanzh<<<128, 256>>>(z);
    k_w<<<32, 256>>>(k2u, u2k);
    k_adj<<<NE / 256, 256>>>(ei);
    k_covm<<<dim3(2, 2, 32), 256, 65536>>>();
    k_cor<<<256, 256>>>();
    k_mcor<<<32, 256>>>();
    k_z2m<<<dim3(64, 2), 256, 65536>>>(z);
    k_norm<<<NN / 8, 256>>>();
    k_edge<<<NE / 8, 256>>>(ei);
    k_sim<<<2080, 256, 65536>>>();
    k_final<<<1, 256>>>(out);
}

// round 15
// speedup vs baseline: 1.4237x; 1.4237x over previous
#include <cuda_runtime.h>
#include <cuda_bf16.h>
#include <math.h>
#include <stdint.h>

#define NN 8192
#define FF 256
#define NE 262144
#define ADJW (NN * (NN / 32))   // 2,097,152 words = 8 MB bitmap

// ---------------- scratch (device globals; no allocation allowed) ----------------
__device__ __align__(256) float    g_meansum[FF];
__device__ __align__(256) float    g_mcor[FF];
__device__ __align__(256) float    g_cov[FF * FF];       // covraw = zh^T zh
__device__ __align__(256) float    g_cor[FF * FF];
__device__ __align__(256) __nv_bfloat16 g_corh[FF * FF];
__device__ __align__(256) float    g_w[NN];
__device__ __align__(256) float    g_z2[NN * FF];        // 8 MB fp32
__device__ __align__(256) __nv_bfloat16 g_zh[NN * FF];   // 4 MB bf16 of z
__device__ __align__(256) __nv_bfloat16 g_z2h[NN * FF];  // 4 MB bf16 of z2
__device__ __align__(256) float    g_invn[NN];
__device__ __align__(256) unsigned g_adj[ADJW];          // 8 MB adjacency bitmap
__device__ __align__(256) float    g_scores[NN];
__device__ __align__(256) float    g_deg[NN];
__device__ double g_penalty;
__device__ int    g_is64;

__device__ __forceinline__ int load_idx(const void* p, int k, int is64) {
    return is64 ? (int)((const long long*)p)[k] : ((const int*)p)[k];
}

__device__ __forceinline__ void detect_is64(const unsigned* e) {
    unsigned acc = 0;
    for (int i = threadIdx.x; i < 2048; i += 256) acc |= e[2 * i + 1];
    int any = __syncthreads_or((int)(acc != 0));
    if (threadIdx.x == 0) g_is64 = any ? 0 : 1;   // benign same-value race across kernels
}

// ---------------- zeroing, split by consumer chain ----------------
// stream1: adjacency bitmap + degree + dtype detect (feeds k_adj)
__global__ void k_zero_adj(const unsigned* __restrict__ e) {
    int idx = blockIdx.x * blockDim.x + threadIdx.x;
    int stride = gridDim.x * blockDim.x;
    for (int i = idx; i < ADJW; i += stride) g_adj[i] = 0u;
    for (int i = idx; i < NN; i += stride) g_deg[i] = 0.0f;
    if (blockIdx.x == 0) detect_is64(e);
}

// stream0: everything else + dtype detect (feeds k_w)
__global__ void k_zero_rest(const unsigned* __restrict__ e) {
    int idx = blockIdx.x * blockDim.x + threadIdx.x;
    int stride = gridDim.x * blockDim.x;
    for (int i = idx; i < FF * FF; i += stride) g_cov[i] = 0.0f;
    for (int i = idx; i < NN; i += stride) g_scores[i] = 0.0f;
    for (int i = idx; i < FF; i += stride) g_meansum[i] = 0.0f;
    if (idx == 0) g_penalty = 0.0;
    if (blockIdx.x == 0) detect_is64(e);
}

// ---------------- fused: column sums + z -> bf16 ----------------
__global__ void k_meanzh(const float* __restrict__ z) {
    int f = threadIdx.x;
    int r0 = blockIdx.x * 64;
    float s = 0.0f;
    #pragma unroll 8
    for (int r = 0; r < 64; ++r) {
        float v = z[(r0 + r) * FF + f];
        s += v;
        g_zh[(r0 + r) * FF + f] = __float2bfloat16(v);
    }
    atomicAdd(&g_meansum[f], s);
}

// ---------------- per-node weight ----------------
__global__ void k_w(const void* __restrict__ k2u, const void* __restrict__ u2k) {
    int n = blockIdx.x * blockDim.x + threadIdx.x;
    int is64 = g_is64;
    if (n < NN) {
        float a = powf(0.9f, (float)load_idx(k2u, n, is64));
        float b = powf(0.9f, (float)load_idx(u2k, n, is64));
        g_w[n] = a + 1.0f - b;
    }
}

// ---------------- adjacency bitmap + degree ----------------
__global__ void k_adj(const void* __restrict__ ei) {
    int e = blockIdx.x * blockDim.x + threadIdx.x;
    int is64 = g_is64;
    if (e < NE) {
        int i = load_idx(ei, e, is64);
        int j = load_idx(ei, NE + e, is64);
        unsigned b1 = (unsigned)i * NN + (unsigned)j;
        atomicOr(&g_adj[b1 >> 5], 1u << (b1 & 31));
        unsigned b2 = (unsigned)j * NN + (unsigned)i;
        atomicOr(&g_adj[b2 >> 5], 1u << (b2 & 31));
        atomicAdd(&g_deg[i], 1.0f);
    }
}

// ---------------- MMA helpers ----------------
__device__ __forceinline__ void ldsm_x4(unsigned addr, unsigned& r0, unsigned& r1,
                                        unsigned& r2, unsigned& r3) {
    asm volatile("ldmatrix.sync.aligned.m8n8.x4.shared.b16 {%0,%1,%2,%3}, [%4];"
                 : "=r"(r0), "=r"(r1), "=r"(r2), "=r"(r3) : "r"(addr));
}

__device__ __forceinline__ void ldsm_x4t(unsigned addr, unsigned& r0, unsigned& r1,
                                         unsigned& r2, unsigned& r3) {
    asm volatile("ldmatrix.sync.aligned.m8n8.x4.trans.shared.b16 {%0,%1,%2,%3}, [%4];"
                 : "=r"(r0), "=r"(r1), "=r"(r2), "=r"(r3) : "r"(addr));
}

__device__ __forceinline__ void mma16816(float* d, const unsigned* a, const unsigned* b) {
    asm volatile(
        "mma.sync.aligned.m16n8k16.row.col.f32.bf16.bf16.f32 "
        "{%0,%1,%2,%3}, {%4,%5,%6,%7}, {%8,%9}, {%0,%1,%2,%3};"
        : "+f"(d[0]), "+f"(d[1]), "+f"(d[2]), "+f"(d[3])
        : "r"(a[0]), "r"(a[1]), "r"(a[2]), "r"(a[3]), "r"(b[0]), "r"(b[1]));
}

__device__ __forceinline__ void cp16(unsigned saddr, const void* gaddr) {
    asm volatile("cp.async.cg.shared.global [%0], [%1], 16;"
                 :: "r"(saddr), "l"(gaddr) : "memory");
}

// ---------------- covraw = zh^T @ zh via HMMA (trans loads), upper tile pairs ----------------
__global__ void __launch_bounds__(256, 2) k_covm() {
    if (blockIdx.x > blockIdx.y) return;
    extern __shared__ char dsm[];
    int i0 = blockIdx.x * 128, j0 = blockIdx.y * 128;
    int r0 = blockIdx.z * 256;
    int tid = threadIdx.x;
    int lane = tid & 31;
    int warp = tid >> 5;
    int wm = warp & 3;
    int wn = warp >> 2;
    unsigned sbase = (unsigned)__cvta_generic_to_shared(dsm);
    unsigned aBase = sbase;
    unsigned bBase = sbase + 32768;
    float acc[2][8][4] = {};

    for (int cc = 0; cc < 2; ++cc) {
        int rr = r0 + cc * 128;
        __syncthreads();
        #pragma unroll
        for (int it = 0; it < 8; ++it) {
            int lin = tid + it * 256;
            int r = lin >> 4, c = lin & 15;
            unsigned soff = (unsigned)(r * 256 + ((c ^ (r & 7)) << 4));
            uint4 va = *((const uint4*)(g_zh + (rr + r) * FF + i0) + c);
            uint4 vb = *((const uint4*)(g_zh + (rr + r) * FF + j0) + c);
            *(uint4*)(dsm + soff) = va;
            *(uint4*)(dsm + 32768 + soff) = vb;
        }
        __syncthreads();
        #pragma unroll
        for (int ks = 0; ks < 8; ++ks) {
            int k0 = ks * 16;
            unsigned a[2][4];
            #pragma unroll
            for (int am = 0; am < 2; ++am) {
                int m0 = wm * 32 + am * 16;
                int rA = k0 + ((lane >> 4) & 1) * 8 + (lane & 7);
                int cA = (m0 >> 3) + ((lane >> 3) & 1);
                unsigned addr = aBase + rA * 256 + ((cA ^ (rA & 7)) << 4);
                ldsm_x4t(addr, a[am][0], a[am][1], a[am][2], a[am][3]);
            }
            unsigned b[8][2];
            #pragma unroll
            for (int bn = 0; bn < 4; ++bn) {
                int n0 = wn * 64 + bn * 16;
                int rB = k0 + ((lane >> 3) & 1) * 8 + (lane & 7);
                int cB = (n0 >> 3) + ((lane >> 4) & 1);
                unsigned addr = bBase + rB * 256 + ((cB ^ (rB & 7)) << 4);
                ldsm_x4t(addr, b[2 * bn][0], b[2 * bn][1], b[2 * bn + 1][0], b[2 * bn + 1][1]);
            }
            #pragma unroll
            for (int am = 0; am < 2; ++am)
                #pragma unroll
                for (int nb = 0; nb < 8; ++nb)
                    mma16816(acc[am][nb], a[am], b[nb]);
        }
    }

    #pragma unroll
    for (int am = 0; am < 2; ++am) {
        #pragma unroll
        for (int nb = 0; nb < 8; ++nb) {
            #pragma unroll
            for (int e = 0; e < 4; ++e) {
                int rl = wm * 32 + am * 16 + (lane >> 2) + ((e >> 1) << 3);
                int cl = wn * 64 + nb * 8 + ((lane & 3) << 1) + (e & 1);
                atomicAdd(&g_cov[(i0 + rl) * FF + (j0 + cl)], acc[am][nb][e]);
            }
        }
    }
}

// ---------------- cor: mean-correct covraw, normalize, clamp ----------------
__global__ void k_cor() {
    int idx = blockIdx.x * blockDim.x + threadIdx.x;
    int i = idx >> 8, j = idx & 255;
    int a = min(i, j), b = max(i, j);
    const float inv = 1.0f / (float)NN;
    float mi = g_meansum[i] * inv, mj = g_meansum[j] * inv;
    float di = g_cov[i * FF + i] - (float)NN * mi * mi;
    float dj = g_cov[j * FF + j] - (float)NN * mj * mj;
    float num = g_cov[a * FF + b] - (float)NN * mi * mj;
    float v = num / sqrtf(di * dj);
    if (v != v) v = 0.0f;
    v = fminf(1.0f, fmaxf(-1.0f, v));
    if (i == j) v = 0.0f;
    g_cor[idx] = v;
    g_corh[idx] = __float2bfloat16(v);
}

// ---------------- mcor[c] = sum_k mean[k] * cor[k,c]  (warp per column) ----------------
__global__ void k_mcor() {
    int warp = threadIdx.x >> 5;
    int lane = threadIdx.x & 31;
    int c = blockIdx.x * 8 + warp;
    const float inv = 1.0f / (float)NN;
    float s = 0.0f;
    #pragma unroll
    for (int k = lane; k < FF; k += 32) s += g_meansum[k] * inv * g_cor[k * FF + c];
    #pragma unroll
    for (int o = 16; o; o >>= 1) s += __shfl_down_sync(0xffffffffu, s, o);
    if (lane == 0) g_mcor[c] = s;
}

// ---------------- z2 = z + 0.01*w*(zh@corh - mcor) : HMMA + cp.async ----------------
__global__ void __launch_bounds__(256, 2) k_z2m(const float* __restrict__ z) {
    extern __shared__ char dsm[];
    int r0 = blockIdx.x * 128, c0 = blockIdx.y * 128;
    int tid = threadIdx.x;
    int lane = tid & 31;
    int warp = tid >> 5;
    int wm = warp & 3;
    int wn = warp >> 2;
    unsigned sbase = (unsigned)__cvta_generic_to_shared(dsm);

    auto load_slab = [&](int s, int bsel) {
        unsigned aB = sbase + bsel * 16384;
        unsigned bB = sbase + 32768 + bsel * 16384;
        #pragma unroll
        for (int it = 0; it < 4; ++it) {
            int lin = tid + it * 256;
            int r = lin >> 3, c = lin & 7;
            unsigned soff = (unsigned)(r * 128 + ((c ^ (r & 7)) << 4));
            cp16(aB + soff, g_zh + (r0 + r) * FF + s * 64 + c * 8);
            cp16(bB + soff, g_corh + (c0 + r) * FF + s * 64 + c * 8);
        }
        asm volatile("cp.async.commit_group;" ::: "memory");
    };

    float acc[2][8][4] = {};
    load_slab(0, 0);
    #pragma unroll
    for (int s = 0; s < 4; ++s) {
        if (s < 3) {
            load_slab(s + 1, (s + 1) & 1);
            asm volatile("cp.async.wait_group 1;" ::: "memory");
        } else {
            asm volatile("cp.async.wait_group 0;" ::: "memory");
        }
        __syncthreads();
        unsigned aBase = sbase + (s & 1) * 16384;
        unsigned bBase = sbase + 32768 + (s & 1) * 16384;
        #pragma unroll
        for (int ks = 0; ks < 4; ++ks) {
            unsigned a[2][4];
            #pragma unroll
            for (int am = 0; am < 2; ++am) {
                int ra = wm * 32 + am * 16 + (lane & 15);
                int ca = 2 * ks + (lane >> 4);
                unsigned addr = aBase + ra * 128 + ((ca ^ (ra & 7)) << 4);
                ldsm_x4(addr, a[am][0], a[am][1], a[am][2], a[am][3]);
            }
            unsigned b[8][2];
            #pragma unroll
            for (int bn = 0; bn < 4; ++bn) {
                int rb = wn * 64 + bn * 16 + (lane & 7) + ((lane >> 4) << 3);
                int cb = 2 * ks + ((lane >> 3) & 1);
                unsigned addr = bBase + rb * 128 + ((cb ^ (rb & 7)) << 4);
                ldsm_x4(addr, b[2 * bn][0], b[2 * bn][1], b[2 * bn + 1][0], b[2 * bn + 1][1]);
            }
            #pragma unroll
            for (int am = 0; am < 2; ++am)
                #pragma unroll
                for (int nb = 0; nb < 8; ++nb)
                    mma16816(acc[am][nb], a[am], b[nb]);
        }
        __syncthreads();
    }

    #pragma unroll
    for (int am = 0; am < 2; ++am) {
        #pragma unroll
        for (int nb = 0; nb < 8; ++nb) {
            #pragma unroll
            for (int e = 0; e < 4; ++e) {
                int rl = wm * 32 + am * 16 + (lane >> 2) + ((e >> 1) << 3);
                int cl = wn * 64 + nb * 8 + ((lane & 3) << 1) + (e & 1);
                int r = r0 + rl, c = c0 + cl;
                g_z2[r * FF + c] = z[r * FF + c]
                                 + 0.01f * g_w[r] * (acc[am][nb][e] - g_mcor[c]);
            }
        }
    }
}

// ---------------- row norms + diag penalty + bf16 copy ----------------
__global__ void k_norm() {
    int gw = (blockIdx.x * blockDim.x + threadIdx.x) >> 5;
    int lane = threadIdx.x & 31;
    if (gw >= NN) return;
    const float4* p = (const float4*)(g_z2 + gw * FF);
    float4 a = p[lane * 2], b = p[lane * 2 + 1];
    union { __nv_bfloat162 h[4]; uint4 u; } cv;
    cv.h[0] = __floats2bfloat162_rn(a.x, a.y);
    cv.h[1] = __floats2bfloat162_rn(a.z, a.w);
    cv.h[2] = __floats2bfloat162_rn(b.x, b.y);
    cv.h[3] = __floats2bfloat162_rn(b.z, b.w);
    *((uint4*)(g_z2h + gw * FF) + lane) = cv.u;

    float s = a.x * a.x + a.y * a.y + a.z * a.z + a.w * a.w
            + b.x * b.x + b.y * b.y + b.z * b.z + b.w * b.w;
    #pragma unroll
    for (int o = 16; o; o >>= 1) s += __shfl_down_sync(0xffffffffu, s, o);
    if (lane == 0) {
        g_invn[gw] = 1.0f / fmaxf(sqrtf(s), 1e-8f);
        unsigned bi = (unsigned)gw * NN + (unsigned)gw;
        unsigned bit = (g_adj[bi >> 5] >> (bi & 31)) & 1u;
        if (s > 0.8f && !bit) atomicAdd(&g_penalty, (double)s);
    }
}

// ---------------- per-edge cosine similarity (bf16 gathers) ----------------
__global__ void k_edge(const void* __restrict__ ei) {
    int gw = (blockIdx.x * blockDim.x + threadIdx.x) >> 5;
    int lane = threadIdx.x & 31;
    if (gw >= NE) return;
    int is64 = g_is64;
    int i = load_idx(ei, gw, is64);
    int j = load_idx(ei, NE + gw, is64);
    union { uint4 u; __nv_bfloat162 h[4]; } ua, ub;
    ua.u = *((const uint4*)(g_z2h + i * FF) + lane);
    ub.u = *((const uint4*)(g_z2h + j * FF) + lane);
    float d = 0.0f;
    #pragma unroll
    for (int q = 0; q < 4; ++q) {
        float2 fa = __bfloat1622float2(ua.h[q]);
        float2 fb = __bfloat1622float2(ub.h[q]);
        d += fa.x * fb.x + fa.y * fb.y;
    }
    #pragma unroll
    for (int o = 16; o; o >>= 1) d += __shfl_down_sync(0xffffffffu, d, o);
    if (lane == 0) atomicAdd(&g_scores[i], d * g_invn[i] * g_invn[j]);
}

// ---------------- masked similarity GEMM (bf16 HMMA + cp.async double buffer) ----------------
__device__ __forceinline__ int cumt(int br) { return br * 64 - (br * (br - 1)) / 2; }

__global__ void __launch_bounds__(256, 2) k_sim() {
    extern __shared__ char dsm[];
    __shared__ unsigned sAdj[512];
    __shared__ float sRed[256];

    int t = blockIdx.x;
    int br = (int)(64.5f - sqrtf(64.5f * 64.5f - 2.0f * (float)t));
    if (br < 0) br = 0; if (br > 63) br = 63;
    while (br < 63 && cumt(br + 1) <= t) br++;
    while (br > 0 && cumt(br) > t) br--;
    int bc = br + (t - cumt(br));
    int r0 = br * 128, c0 = bc * 128;

    int tid = threadIdx.x;
    int lane = tid & 31;
    int warp = tid >> 5;
    int wm = warp & 3;
    int wn = warp >> 2;

    for (int s2 = tid; s2 < 512; s2 += 256)
        sAdj[s2] = g_adj[(r0 + (s2 >> 2)) * (NN / 32) + (c0 >> 5) + (s2 & 3)];

    unsigned sbase = (unsigned)__cvta_generic_to_shared(dsm);

    auto load_slab = [&](int s, int bsel) {
        unsigned aB = sbase + bsel * 16384;
        unsigned bB = sbase + 32768 + bsel * 16384;
        #pragma unroll
        for (int it = 0; it < 4; ++it) {
            int lin = tid + it * 256;
            int r = lin >> 3, c = lin & 7;
            unsigned soff = (unsigned)(r * 128 + ((c ^ (r & 7)) << 4));
            cp16(aB + soff, g_z2h + (r0 + r) * FF + s * 64 + c * 8);
            cp16(bB + soff, g_z2h + (c0 + r) * FF + s * 64 + c * 8);
        }
        asm volatile("cp.async.commit_group;" ::: "memory");
    };

    float acc[2][8][4] = {};
    load_slab(0, 0);
    #pragma unroll
    for (int s = 0; s < 4; ++s) {
        if (s < 3) {
            load_slab(s + 1, (s + 1) & 1);
            asm volatile("cp.async.wait_group 1;" ::: "memory");
        } else {
            asm volatile("cp.async.wait_group 0;" ::: "memory");
        }
        __syncthreads();
        unsigned aBase = sbase + (s & 1) * 16384;
        unsigned bBase = sbase + 32768 + (s & 1) * 16384;
        #pragma unroll
        for (int ks = 0; ks < 4; ++ks) {
            unsigned a[2][4];
            #pragma unroll
            for (int am = 0; am < 2; ++am) {
                int ra = wm * 32 + am * 16 + (lane & 15);
                int ca = 2 * ks + (lane >> 4);
                unsigned addr = aBase + ra * 128 + ((ca ^ (ra & 7)) << 4);
                ldsm_x4(addr, a[am][0], a[am][1], a[am][2], a[am][3]);
            }
            unsigned b[8][2];
            #pragma unroll
            for (int bn = 0; bn < 4; ++bn) {
                int rb = wn * 64 + bn * 16 + (lane & 7) + ((lane >> 4) << 3);
                int cb = 2 * ks + ((lane >> 3) & 1);
                unsigned addr = bBase + rb * 128 + ((cb ^ (rb & 7)) << 4);
                ldsm_x4(addr, b[2 * bn][0], b[2 * bn][1], b[2 * bn + 1][0], b[2 * bn + 1][1]);
            }
            #pragma unroll
            for (int am = 0; am < 2; ++am)
                #pragma unroll
                for (int nb = 0; nb < 8; ++nb)
                    mma16816(acc[am][nb], a[am], b[nb]);
        }
        __syncthreads();
    }

    bool diagBlk = (br == bc);
    float lsum = 0.0f;
    #pragma unroll
    for (int am = 0; am < 2; ++am) {
        #pragma unroll
        for (int nb = 0; nb < 8; ++nb) {
            #pragma unroll
            for (int e = 0; e < 4; ++e) {
                int rl = wm * 32 + am * 16 + (lane >> 2) + ((e >> 1) << 3);
                int cl = wn * 64 + nb * 8 + ((lane & 3) << 1) + (e & 1);
                float val = acc[am][nb][e];
                unsigned bit = (sAdj[rl * 4 + (cl >> 5)] >> (cl & 31)) & 1u;
                if (val > 0.8f && !bit && (!diagBlk || cl > rl)) lsum += val;
            }
        }
    }
    sRed[tid] = lsum;
    __syncthreads();
    for (int o = 128; o; o >>= 1) {
        if (tid < o) sRed[tid] += sRed[tid + o];
        __syncthreads();
    }
    if (tid == 0) atomicAdd(&g_penalty, 2.0 * (double)sRed[0]);
}

// ---------------- final scalar ----------------
__global__ void k_final(float* __restrict__ out) {
    __shared__ double sred[256];
    int tid = threadIdx.x;
    double s = 0.0;
    for (int n = tid; n < NN; n += 256) {
        float d = g_deg[n];
        if (d == 0.0f) d = 1.0f;
        s += (double)(g_scores[n] / d);
    }
    sred[tid] = s;
    __syncthreads();
    for (int o = 128; o; o >>= 1) {
        if (tid < o) sred[tid] += sred[tid + o];
        __syncthreads();
    }
    if (tid == 0) {
        double hom = -sred[0] / (double)NN;
        double pen = g_penalty / ((double)NN * (double)NN);
        out[0] = (float)(hom + pen);
    }
}

// ---------------- launch (fork-join overlap on a side stream) ----------------
extern "C" void kernel_launch(void* const* d_in, const int* in_sizes, int n_in,
                              void* d_out, int out_size) {
    const float* z   = (const float*)d_in[0];
    const void* ei   = d_in[2];
    const void* k2u  = d_in[3];
    const void* u2k  = d_in[4];
    float* out = (float*)d_out;

    static cudaStream_t s1 = nullptr;
    static cudaEvent_t evFork = nullptr, evAdj = nullptr, evFork2 = nullptr, evEdge = nullptr;
    if (!s1) {
        cudaStreamCreateWithFlags(&s1, cudaStreamNonBlocking);
        cudaEventCreateWithFlags(&evFork, cudaEventDisableTiming);
        cudaEventCreateWithFlags(&evAdj, cudaEventDisableTiming);
        cudaEventCreateWithFlags(&evFork2, cudaEventDisableTiming);
        cudaEventCreateWithFlags(&evEdge, cudaEventDisableTiming);
        cudaFuncSetAttribute(k_sim, cudaFuncAttributeMaxDynamicSharedMemorySize, 65536);
        cudaFuncSetAttribute(k_z2m, cudaFuncAttributeMaxDynamicSharedMemorySize, 65536);
        cudaFuncSetAttribute(k_covm, cudaFuncAttributeMaxDynamicSharedMemorySize, 65536);
    }

    // fork: adjacency chain on side stream
    cudaEventRecord(evFork, 0);
    cudaStreamWaitEvent(s1, evFork, 0);
    k_zero_adj<<<2048, 256, 0, s1>>>((const unsigned*)ei);
    k_adj<<<NE / 256, 256, 0, s1>>>(ei);
    cudaEventRecord(evAdj, s1);

    // main chain
    k_zero_rest<<<512, 256>>>((const unsigned*)ei);
    k_meanzh<<<128, 256>>>(z);
    k_w<<<32, 256>>>(k2u, u2k);
    k_covm<<<dim3(2, 2, 32), 256, 65536>>>();
    k_cor<<<256, 256>>>();
    k_mcor<<<32, 256>>>();
    k_z2m<<<dim3(64, 2), 256, 65536>>>(z);

    // join adjacency before k_norm (diag bit) / k_sim / k_edge
    cudaStreamWaitEvent(0, evAdj, 0);
    k_norm<<<NN / 8, 256>>>();

    // fork 2: k_edge overlaps k_sim
    cudaEventRecord(evFork2, 0);
    cudaStreamWaitEvent(s1, evFork2, 0);
    k_edge<<<NE / 8, 256, 0, s1>>>(ei);
    cudaEventRecord(evEdge, s1);

    k_sim<<<2080, 256, 65536>>>();

    // join before final
    cudaStreamWaitEvent(0, evEdge, 0);
    k_final<<<1, 256>>>(out);
}

// round 16
// speedup vs baseline: 1.4340x; 1.0072x over previous
#include <cuda_runtime.h>
#include <cuda_bf16.h>
#include <math.h>
#include <stdint.h>

#define NN 8192
#define FF 256
#define NE 262144
#define ADJW (NN * (NN / 32))   // 2,097,152 words = 8 MB bitmap

// ---------------- scratch (device globals; no allocation allowed) ----------------
__device__ __align__(256) float    g_meansum[FF];
__device__ __align__(256) float    g_mcor[FF];
__device__ __align__(256) float    g_cov[FF * FF];       // covraw = zh^T zh
__device__ __align__(256) float    g_cor[FF * FF];
__device__ __align__(256) __nv_bfloat16 g_corh[FF * FF];
__device__ __align__(256) float    g_w[NN];
__device__ __align__(256) float    g_z2[NN * FF];        // 8 MB fp32
__device__ __align__(256) __nv_bfloat16 g_zh[NN * FF];   // 4 MB bf16 of z
__device__ __align__(256) __nv_bfloat16 g_z2h[NN * FF];  // 4 MB bf16 of z2
__device__ __align__(256) float    g_invn[NN];
__device__ __align__(256) unsigned g_adj[ADJW];          // 8 MB adjacency bitmap
__device__ __align__(256) float    g_scores[NN];
__device__ __align__(256) float    g_deg[NN];
__device__ double g_penalty;
__device__ int    g_is64;

__device__ __forceinline__ int load_idx(const void* p, int k, int is64) {
    return is64 ? (int)((const long long*)p)[k] : ((const int*)p)[k];
}

__device__ __forceinline__ void detect_is64(const unsigned* e) {
    unsigned acc = 0;
    for (int i = threadIdx.x; i < 2048; i += 256) acc |= e[2 * i + 1];
    int any = __syncthreads_or((int)(acc != 0));
    if (threadIdx.x == 0) g_is64 = any ? 0 : 1;   // benign same-value race across kernels
}

// ---------------- zeroing, split by consumer chain ----------------
__global__ void k_zero_adj(const unsigned* __restrict__ e) {
    int idx = blockIdx.x * blockDim.x + threadIdx.x;
    int stride = gridDim.x * blockDim.x;
    for (int i = idx; i < ADJW; i += stride) g_adj[i] = 0u;
    for (int i = idx; i < NN; i += stride) g_deg[i] = 0.0f;
    if (blockIdx.x == 0) detect_is64(e);
}

__global__ void k_zero_rest(const unsigned* __restrict__ e) {
    int idx = blockIdx.x * blockDim.x + threadIdx.x;
    int stride = gridDim.x * blockDim.x;
    for (int i = idx; i < FF * FF; i += stride) g_cov[i] = 0.0f;
    for (int i = idx; i < NN; i += stride) g_scores[i] = 0.0f;
    for (int i = idx; i < FF; i += stride) g_meansum[i] = 0.0f;
    if (idx == 0) g_penalty = 0.0;
    if (blockIdx.x == 0) detect_is64(e);
}

// ---------------- fused: column sums + z -> bf16  (512 blocks x 16 rows) ----------------
__global__ void k_meanzh(const float* __restrict__ z) {
    int f = threadIdx.x;
    int r0 = blockIdx.x * 16;
    float s = 0.0f;
    #pragma unroll
    for (int r = 0; r < 16; ++r) {
        float v = z[(r0 + r) * FF + f];
        s += v;
        g_zh[(r0 + r) * FF + f] = __float2bfloat16(v);
    }
    atomicAdd(&g_meansum[f], s);
}

// ---------------- per-node weight ----------------
__global__ void k_w(const void* __restrict__ k2u, const void* __restrict__ u2k) {
    int n = blockIdx.x * blockDim.x + threadIdx.x;
    int is64 = g_is64;
    if (n < NN) {
        float a = powf(0.9f, (float)load_idx(k2u, n, is64));
        float b = powf(0.9f, (float)load_idx(u2k, n, is64));
        g_w[n] = a + 1.0f - b;
    }
}

// ---------------- adjacency bitmap + degree ----------------
__global__ void k_adj(const void* __restrict__ ei) {
    int e = blockIdx.x * blockDim.x + threadIdx.x;
    int is64 = g_is64;
    if (e < NE) {
        int i = load_idx(ei, e, is64);
        int j = load_idx(ei, NE + e, is64);
        unsigned b1 = (unsigned)i * NN + (unsigned)j;
        atomicOr(&g_adj[b1 >> 5], 1u << (b1 & 31));
        unsigned b2 = (unsigned)j * NN + (unsigned)i;
        atomicOr(&g_adj[b2 >> 5], 1u << (b2 & 31));
        atomicAdd(&g_deg[i], 1.0f);
    }
}

// ---------------- MMA helpers ----------------
__device__ __forceinline__ void ldsm_x4(unsigned addr, unsigned& r0, unsigned& r1,
                                        unsigned& r2, unsigned& r3) {
    asm volatile("ldmatrix.sync.aligned.m8n8.x4.shared.b16 {%0,%1,%2,%3}, [%4];"
                 : "=r"(r0), "=r"(r1), "=r"(r2), "=r"(r3) : "r"(addr));
}

__device__ __forceinline__ void ldsm_x4t(unsigned addr, unsigned& r0, unsigned& r1,
                                         unsigned& r2, unsigned& r3) {
    asm volatile("ldmatrix.sync.aligned.m8n8.x4.trans.shared.b16 {%0,%1,%2,%3}, [%4];"
                 : "=r"(r0), "=r"(r1), "=r"(r2), "=r"(r3) : "r"(addr));
}

__device__ __forceinline__ void mma16816(float* d, const unsigned* a, const unsigned* b) {
    asm volatile(
        "mma.sync.aligned.m16n8k16.row.col.f32.bf16.bf16.f32 "
        "{%0,%1,%2,%3}, {%4,%5,%6,%7}, {%8,%9}, {%0,%1,%2,%3};"
        : "+f"(d[0]), "+f"(d[1]), "+f"(d[2]), "+f"(d[3])
        : "r"(a[0]), "r"(a[1]), "r"(a[2]), "r"(a[3]), "r"(b[0]), "r"(b[1]));
}

__device__ __forceinline__ void cp16(unsigned saddr, const void* gaddr) {
    asm volatile("cp.async.cg.shared.global [%0], [%1], 16;"
                 :: "r"(saddr), "l"(gaddr) : "memory");
}

// ---------------- covraw = zh^T @ zh via HMMA (trans loads), upper tile pairs ----------------
__global__ void __launch_bounds__(256, 2) k_covm() {
    if (blockIdx.x > blockIdx.y) return;
    extern __shared__ char dsm[];
    int i0 = blockIdx.x * 128, j0 = blockIdx.y * 128;
    int r0 = blockIdx.z * 256;
    int tid = threadIdx.x;
    int lane = tid & 31;
    int warp = tid >> 5;
    int wm = warp & 3;
    int wn = warp >> 2;
    unsigned sbase = (unsigned)__cvta_generic_to_shared(dsm);
    unsigned aBase = sbase;
    unsigned bBase = sbase + 32768;
    float acc[2][8][4] = {};

    for (int cc = 0; cc < 2; ++cc) {
        int rr = r0 + cc * 128;
        __syncthreads();
        #pragma unroll
        for (int it = 0; it < 8; ++it) {
            int lin = tid + it * 256;
            int r = lin >> 4, c = lin & 15;
            unsigned soff = (unsigned)(r * 256 + ((c ^ (r & 7)) << 4));
            uint4 va = *((const uint4*)(g_zh + (rr + r) * FF + i0) + c);
            uint4 vb = *((const uint4*)(g_zh + (rr + r) * FF + j0) + c);
            *(uint4*)(dsm + soff) = va;
            *(uint4*)(dsm + 32768 + soff) = vb;
        }
        __syncthreads();
        #pragma unroll
        for (int ks = 0; ks < 8; ++ks) {
            int k0 = ks * 16;
            unsigned a[2][4];
            #pragma unroll
            for (int am = 0; am < 2; ++am) {
                int m0 = wm * 32 + am * 16;
                int rA = k0 + ((lane >> 4) & 1) * 8 + (lane & 7);
                int cA = (m0 >> 3) + ((lane >> 3) & 1);
                unsigned addr = aBase + rA * 256 + ((cA ^ (rA & 7)) << 4);
                ldsm_x4t(addr, a[am][0], a[am][1], a[am][2], a[am][3]);
            }
            unsigned b[8][2];
            #pragma unroll
            for (int bn = 0; bn < 4; ++bn) {
                int n0 = wn * 64 + bn * 16;
                int rB = k0 + ((lane >> 3) & 1) * 8 + (lane & 7);
                int cB = (n0 >> 3) + ((lane >> 4) & 1);
                unsigned addr = bBase + rB * 256 + ((cB ^ (rB & 7)) << 4);
                ldsm_x4t(addr, b[2 * bn][0], b[2 * bn][1], b[2 * bn + 1][0], b[2 * bn + 1][1]);
            }
            #pragma unroll
            for (int am = 0; am < 2; ++am)
                #pragma unroll
                for (int nb = 0; nb < 8; ++nb)
                    mma16816(acc[am][nb], a[am], b[nb]);
        }
    }

    #pragma unroll
    for (int am = 0; am < 2; ++am) {
        #pragma unroll
        for (int nb = 0; nb < 8; ++nb) {
            #pragma unroll
            for (int e = 0; e < 4; ++e) {
                int rl = wm * 32 + am * 16 + (lane >> 2) + ((e >> 1) << 3);
                int cl = wn * 64 + nb * 8 + ((lane & 3) << 1) + (e & 1);
                atomicAdd(&g_cov[(i0 + rl) * FF + (j0 + cl)], acc[am][nb][e]);
            }
        }
    }
}

// ---------------- cor: mean-correct covraw, normalize, clamp ----------------
__global__ void k_cor() {
    int idx = blockIdx.x * blockDim.x + threadIdx.x;
    int i = idx >> 8, j = idx & 255;
    int a = min(i, j), b = max(i, j);
    const float inv = 1.0f / (float)NN;
    float mi = g_meansum[i] * inv, mj = g_meansum[j] * inv;
    float di = g_cov[i * FF + i] - (float)NN * mi * mi;
    float dj = g_cov[j * FF + j] - (float)NN * mj * mj;
    float num = g_cov[a * FF + b] - (float)NN * mi * mj;
    float v = num / sqrtf(di * dj);
    if (v != v) v = 0.0f;
    v = fminf(1.0f, fmaxf(-1.0f, v));
    if (i == j) v = 0.0f;
    g_cor[idx] = v;
    g_corh[idx] = __float2bfloat16(v);
}

// ---------------- mcor[c] = sum_k mean[k] * cor[k,c]  (warp per column) ----------------
__global__ void k_mcor() {
    int warp = threadIdx.x >> 5;
    int lane = threadIdx.x & 31;
    int c = blockIdx.x * 8 + warp;
    const float inv = 1.0f / (float)NN;
    float s = 0.0f;
    #pragma unroll
    for (int k = lane; k < FF; k += 32) s += g_meansum[k] * inv * g_cor[k * FF + c];
    #pragma unroll
    for (int o = 16; o; o >>= 1) s += __shfl_down_sync(0xffffffffu, s, o);
    if (lane == 0) g_mcor[c] = s;
}

// ---------------- z2 = z + 0.01*w*(zh@corh - mcor) : HMMA + cp.async ----------------
__global__ void __launch_bounds__(256, 2) k_z2m(const float* __restrict__ z) {
    extern __shared__ char dsm[];
    int r0 = blockIdx.x * 128, c0 = blockIdx.y * 128;
    int tid = threadIdx.x;
    int lane = tid & 31;
    int warp = tid >> 5;
    int wm = warp & 3;
    int wn = warp >> 2;
    unsigned sbase = (unsigned)__cvta_generic_to_shared(dsm);

    auto load_slab = [&](int s, int bsel) {
        unsigned aB = sbase + bsel * 16384;
        unsigned bB = sbase + 32768 + bsel * 16384;
        #pragma unroll
        for (int it = 0; it < 4; ++it) {
            int lin = tid + it * 256;
            int r = lin >> 3, c = lin & 7;
            unsigned soff = (unsigned)(r * 128 + ((c ^ (r & 7)) << 4));
            cp16(aB + soff, g_zh + (r0 + r) * FF + s * 64 + c * 8);
            cp16(bB + soff, g_corh + (c0 + r) * FF + s * 64 + c * 8);
        }
        asm volatile("cp.async.commit_group;" ::: "memory");
    };

    float acc[2][8][4] = {};
    load_slab(0, 0);
    #pragma unroll
    for (int s = 0; s < 4; ++s) {
        if (s < 3) {
            load_slab(s + 1, (s + 1) & 1);
            asm volatile("cp.async.wait_group 1;" ::: "memory");
        } else {
            asm volatile("cp.async.wait_group 0;" ::: "memory");
        }
        __syncthreads();
        unsigned aBase = sbase + (s & 1) * 16384;
        unsigned bBase = sbase + 32768 + (s & 1) * 16384;
        #pragma unroll
        for (int ks = 0; ks < 4; ++ks) {
            unsigned a[2][4];
            #pragma unroll
            for (int am = 0; am < 2; ++am) {
                int ra = wm * 32 + am * 16 + (lane & 15);
                int ca = 2 * ks + (lane >> 4);
                unsigned addr = aBase + ra * 128 + ((ca ^ (ra & 7)) << 4);
                ldsm_x4(addr, a[am][0], a[am][1], a[am][2], a[am][3]);
            }
            unsigned b[8][2];
            #pragma unroll
            for (int bn = 0; bn < 4; ++bn) {
                int rb = wn * 64 + bn * 16 + (lane & 7) + ((lane >> 4) << 3);
                int cb = 2 * ks + ((lane >> 3) & 1);
                unsigned addr = bBase + rb * 128 + ((cb ^ (rb & 7)) << 4);
                ldsm_x4(addr, b[2 * bn][0], b[2 * bn][1], b[2 * bn + 1][0], b[2 * bn + 1][1]);
            }
            #pragma unroll
            for (int am = 0; am < 2; ++am)
                #pragma unroll
                for (int nb = 0; nb < 8; ++nb)
                    mma16816(acc[am][nb], a[am], b[nb]);
        }
        __syncthreads();
    }

    #pragma unroll
    for (int am = 0; am < 2; ++am) {
        #pragma unroll
        for (int nb = 0; nb < 8; ++nb) {
            #pragma unroll
            for (int e = 0; e < 4; ++e) {
                int rl = wm * 32 + am * 16 + (lane >> 2) + ((e >> 1) << 3);
                int cl = wn * 64 + nb * 8 + ((lane & 3) << 1) + (e & 1);
                int r = r0 + rl, c = c0 + cl;
                g_z2[r * FF + c] = z[r * FF + c]
                                 + 0.01f * g_w[r] * (acc[am][nb][e] - g_mcor[c]);
            }
        }
    }
}

// ---------------- row norms + diag penalty + bf16 copy ----------------
__global__ void k_norm() {
    int gw = (blockIdx.x * blockDim.x + threadIdx.x) >> 5;
    int lane = threadIdx.x & 31;
    if (gw >= NN) return;
    const float4* p = (const float4*)(g_z2 + gw * FF);
    float4 a = p[lane * 2], b = p[lane * 2 + 1];
    union { __nv_bfloat162 h[4]; uint4 u; } cv;
    cv.h[0] = __floats2bfloat162_rn(a.x, a.y);
    cv.h[1] = __floats2bfloat162_rn(a.z, a.w);
    cv.h[2] = __floats2bfloat162_rn(b.x, b.y);
    cv.h[3] = __floats2bfloat162_rn(b.z, b.w);
    *((uint4*)(g_z2h + gw * FF) + lane) = cv.u;

    float s = a.x * a.x + a.y * a.y + a.z * a.z + a.w * a.w
            + b.x * b.x + b.y * b.y + b.z * b.z + b.w * b.w;
    #pragma unroll
    for (int o = 16; o; o >>= 1) s += __shfl_down_sync(0xffffffffu, s, o);
    if (lane == 0) {
        g_invn[gw] = 1.0f / fmaxf(sqrtf(s), 1e-8f);
        unsigned bi = (unsigned)gw * NN + (unsigned)gw;
        unsigned bit = (g_adj[bi >> 5] >> (bi & 31)) & 1u;
        if (s > 0.8f && !bit) atomicAdd(&g_penalty, (double)s);
    }
}

// ---------------- per-edge cosine similarity (bf16 gathers) ----------------
__global__ void k_edge(const void* __restrict__ ei) {
    int gw = (blockIdx.x * blockDim.x + threadIdx.x) >> 5;
    int lane = threadIdx.x & 31;
    if (gw >= NE) return;
    int is64 = g_is64;
    int i = load_idx(ei, gw, is64);
    int j = load_idx(ei, NE + gw, is64);
    union { uint4 u; __nv_bfloat162 h[4]; } ua, ub;
    ua.u = *((const uint4*)(g_z2h + i * FF) + lane);
    ub.u = *((const uint4*)(g_z2h + j * FF) + lane);
    float d = 0.0f;
    #pragma unroll
    for (int q = 0; q < 4; ++q) {
        float2 fa = __bfloat1622float2(ua.h[q]);
        float2 fb = __bfloat1622float2(ub.h[q]);
        d += fa.x * fb.x + fa.y * fb.y;
    }
    #pragma unroll
    for (int o = 16; o; o >>= 1) d += __shfl_down_sync(0xffffffffu, d, o);
    if (lane == 0) atomicAdd(&g_scores[i], d * g_invn[i] * g_invn[j]);
}

// ---------------- masked similarity GEMM (bf16 HMMA, persistent CTAs) ----------------
__device__ __forceinline__ int cumt(int br) { return br * 64 - (br * (br - 1)) / 2; }

#define SIM_TILES 2080
#define SIM_GRID  296

__global__ void __launch_bounds__(256, 2) k_sim() {
    extern __shared__ char dsm[];
    __shared__ unsigned sAdj[512];
    __shared__ float sRed[256];

    int tid = threadIdx.x;
    int lane = tid & 31;
    int warp = tid >> 5;
    int wm = warp & 3;
    int wn = warp >> 2;
    unsigned sbase = (unsigned)__cvta_generic_to_shared(dsm);

    for (int t = blockIdx.x; t < SIM_TILES; t += SIM_GRID) {
        int br = (int)(64.5f - sqrtf(64.5f * 64.5f - 2.0f * (float)t));
        if (br < 0) br = 0; if (br > 63) br = 63;
        while (br < 63 && cumt(br + 1) <= t) br++;
        while (br > 0 && cumt(br) > t) br--;
        int bc = br + (t - cumt(br));
        int r0 = br * 128, c0 = bc * 128;

        for (int s2 = tid; s2 < 512; s2 += 256)
            sAdj[s2] = g_adj[(r0 + (s2 >> 2)) * (NN / 32) + (c0 >> 5) + (s2 & 3)];

        auto load_slab = [&](int s, int bsel) {
            unsigned aB = sbase + bsel * 16384;
            unsigned bB = sbase + 32768 + bsel * 16384;
            #pragma unroll
            for (int it = 0; it < 4; ++it) {
                int lin = tid + it * 256;
                int r = lin >> 3, c = lin & 7;
                unsigned soff = (unsigned)(r * 128 + ((c ^ (r & 7)) << 4));
                cp16(aB + soff, g_z2h + (r0 + r) * FF + s * 64 + c * 8);
                cp16(bB + soff, g_z2h + (c0 + r) * FF + s * 64 + c * 8);
            }
            asm volatile("cp.async.commit_group;" ::: "memory");
        };

        float acc[2][8][4] = {};
        load_slab(0, 0);
        #pragma unroll
        for (int s = 0; s < 4; ++s) {
            if (s < 3) {
                load_slab(s + 1, (s + 1) & 1);
                asm volatile("cp.async.wait_group 1;" ::: "memory");
            } else {
                asm volatile("cp.async.wait_group 0;" ::: "memory");
            }
            __syncthreads();
            unsigned aBase = sbase + (s & 1) * 16384;
            unsigned bBase = sbase + 32768 + (s & 1) * 16384;
            #pragma unroll
            for (int ks = 0; ks < 4; ++ks) {
                unsigned a[2][4];
                #pragma unroll
                for (int am = 0; am < 2; ++am) {
                    int ra = wm * 32 + am * 16 + (lane & 15);
                    int ca = 2 * ks + (lane >> 4);
                    unsigned addr = aBase + ra * 128 + ((ca ^ (ra & 7)) << 4);
                    ldsm_x4(addr, a[am][0], a[am][1], a[am][2], a[am][3]);
                }
                unsigned b[8][2];
                #pragma unroll
                for (int bn = 0; bn < 4; ++bn) {
                    int rb = wn * 64 + bn * 16 + (lane & 7) + ((lane >> 4) << 3);
                    int cb = 2 * ks + ((lane >> 3) & 1);
                    unsigned addr = bBase + rb * 128 + ((cb ^ (rb & 7)) << 4);
                    ldsm_x4(addr, b[2 * bn][0], b[2 * bn][1], b[2 * bn + 1][0], b[2 * bn + 1][1]);
                }
                #pragma unroll
                for (int am = 0; am < 2; ++am)
                    #pragma unroll
                    for (int nb = 0; nb < 8; ++nb)
                        mma16816(acc[am][nb], a[am], b[nb]);
            }
            __syncthreads();
        }

        bool diagBlk = (br == bc);
        float lsum = 0.0f;
        #pragma unroll
        for (int am = 0; am < 2; ++am) {
            #pragma unroll
            for (int nb = 0; nb < 8; ++nb) {
                #pragma unroll
                for (int e = 0; e < 4; ++e) {
                    int rl = wm * 32 + am * 16 + (lane >> 2) + ((e >> 1) << 3);
                    int cl = wn * 64 + nb * 8 + ((lane & 3) << 1) + (e & 1);
                    float val = acc[am][nb][e];
                    unsigned bit = (sAdj[rl * 4 + (cl >> 5)] >> (cl & 31)) & 1u;
                    if (val > 0.8f && !bit && (!diagBlk || cl > rl)) lsum += val;
                }
            }
        }
        sRed[tid] = lsum;
        __syncthreads();
        for (int o = 128; o; o >>= 1) {
            if (tid < o) sRed[tid] += sRed[tid + o];
            __syncthreads();
        }
        if (tid == 0) atomicAdd(&g_penalty, 2.0 * (double)sRed[0]);
        __syncthreads();
    }
}

// ---------------- final scalar ----------------
__global__ void k_final(float* __restrict__ out) {
    __shared__ double sred[256];
    int tid = threadIdx.x;
    double s = 0.0;
    for (int n = tid; n < NN; n += 256) {
        float d = g_deg[n];
        if (d == 0.0f) d = 1.0f;
        s += (double)(g_scores[n] / d);
    }
    sred[tid] = s;
    __syncthreads();
    for (int o = 128; o; o >>= 1) {
        if (tid < o) sred[tid] += sred[tid + o];
        __syncthreads();
    }
    if (tid == 0) {
        double hom = -sred[0] / (double)NN;
        double pen = g_penalty / ((double)NN * (double)NN);
        out[0] = (float)(hom + pen);
    }
}

// ---------------- launch (fork-join overlap on a side stream) ----------------
extern "C" void kernel_launch(void* const* d_in, const int* in_sizes, int n_in,
                              void* d_out, int out_size) {
    const float* z   = (const float*)d_in[0];
    const void* ei   = d_in[2];
    const void* k2u  = d_in[3];
    const void* u2k  = d_in[4];
    float* out = (float*)d_out;

    static cudaStream_t s1 = nullptr;
    static cudaEvent_t evFork = nullptr, evAdj = nullptr, evFork2 = nullptr, evEdge = nullptr;
    if (!s1) {
        cudaStreamCreateWithFlags(&s1, cudaStreamNonBlocking);
        cudaEventCreateWithFlags(&evFork, cudaEventDisableTiming);
        cudaEventCreateWithFlags(&evAdj, cudaEventDisableTiming);
        cudaEventCreateWithFlags(&evFork2, cudaEventDisableTiming);
        cudaEventCreateWithFlags(&evEdge, cudaEventDisableTiming);
        cudaFuncSetAttribute(k_sim, cudaFuncAttributeMaxDynamicSharedMemorySize, 65536);
        cudaFuncSetAttribute(k_z2m, cudaFuncAttributeMaxDynamicSharedMemorySize, 65536);
        cudaFuncSetAttribute(k_covm, cudaFuncAttributeMaxDynamicSharedMemorySize, 65536);
    }

    // fork: adjacency chain + node weights on side stream
    cudaEventRecord(evFork, 0);
    cudaStreamWaitEvent(s1, evFork, 0);
    k_zero_adj<<<2048, 256, 0, s1>>>((const unsigned*)ei);
    k_w<<<32, 256, 0, s1>>>(k2u, u2k);
    k_adj<<<NE / 256, 256, 0, s1>>>(ei);
    cudaEventRecord(evAdj, s1);

    // main chain
    k_zero_rest<<<512, 256>>>((const unsigned*)ei);
    k_meanzh<<<512, 256>>>(z);
    k_covm<<<dim3(2, 2, 32), 256, 65536>>>();
    k_cor<<<256, 256>>>();
    k_mcor<<<32, 256>>>();
    // join adjacency (k_w feeds z2m epilogue; adj feeds norm/sim)
    cudaStreamWaitEvent(0, evAdj, 0);
    k_z2m<<<dim3(64, 2), 256, 65536>>>(z);
    k_norm<<<NN / 8, 256>>>();

    // fork 2: k_edge overlaps k_sim
    cudaEventRecord(evFork2, 0);
    cudaStreamWaitEvent(s1, evFork2, 0);
    k_edge<<<NE / 8, 256, 0, s1>>>(ei);
    cudaEventRecord(evEdge, s1);

    k_sim<<<SIM_GRID, 256, 65536>>>();

    // join before final
    cudaStreamWaitEvent(0, evEdge, 0);
    k_final<<<1, 256>>>(out);
}